// round 15
// baseline (speedup 1.0000x reference)
#include <cuda_runtime.h>
#include <cuda_bf16.h>

// RAM multi-step transformer — single kernel (pack_conn node eliminated).
//  * state/out conn hoisted into u16-packed registers, packed in-kernel from
//    i32 loads (lo | hi<<16) — identical loop-body form to R13, but no
//    serial pre-kernel + graph-node gap per replay.
//  * in-phase conn read directly as i32 int4s (L2-resident, overlapped).
//  * table loads: .nc + L2::64B fills; evict_last on in/out, fractional on
//    state (policies measured inert, kept from the 27.1us baseline).
//
// x: (256,1024) i32 | conn_in: (2048,16) | conn_state: (1024,16) | conn_out: (512,16)
// mem_in: (2048,65536) f32 | mem_state: (1024,65536) f32 | mem_out: (512,65536) f32
// out: (256,512) f32

#define BATCH 256
#define IN_BITS 1024
#define N_IN 2048
#define N_ST 1024
#define N_OUT 512
#define TBL 65536
#define MAX_ITERS 4
#define THREADS 256

__device__ __forceinline__ unsigned long long mk_policy_pin() {
    unsigned long long pol;
    asm("createpolicy.fractional.L2::evict_last.b64 %0, 1.0;" : "=l"(pol));
    return pol;
}
__device__ __forceinline__ unsigned long long mk_policy_state() {
    unsigned long long pol;
    asm("createpolicy.fractional.L2::evict_last.L2::evict_first.b64 %0, 0.25;" : "=l"(pol));
    return pol;
}
__device__ __forceinline__ float ld_tbl64(const float* p, unsigned long long pol) {
    float v;
    asm("ld.global.nc.L2::cache_hint.L2::64B.f32 %0, [%1], %2;"
        : "=f"(v) : "l"(p), "l"(pol));
    return v;
}

__device__ __forceinline__ unsigned bitw(const unsigned* __restrict__ sw, unsigned idx) {
    return (sw[idx >> 5] >> (idx & 31)) & 1u;
}

// 16-bit address from four int4s of i32 indices (in-phase).
__device__ __forceinline__ unsigned gather16i(const unsigned* __restrict__ sw,
                                              int4 c0, int4 c1, int4 c2, int4 c3) {
    unsigned a = 0;
    a |= bitw(sw, c0.x) << 0;  a |= bitw(sw, c0.y) << 1;
    a |= bitw(sw, c0.z) << 2;  a |= bitw(sw, c0.w) << 3;
    a |= bitw(sw, c1.x) << 4;  a |= bitw(sw, c1.y) << 5;
    a |= bitw(sw, c1.z) << 6;  a |= bitw(sw, c1.w) << 7;
    a |= bitw(sw, c2.x) << 8;  a |= bitw(sw, c2.y) << 9;
    a |= bitw(sw, c2.z) << 10; a |= bitw(sw, c2.w) << 11;
    a |= bitw(sw, c3.x) << 12; a |= bitw(sw, c3.y) << 13;
    a |= bitw(sw, c3.z) << 14; a |= bitw(sw, c3.w) << 15;
    return a;
}

// 16-bit address from two int4s holding 16 packed u16 indices (state/out).
__device__ __forceinline__ unsigned gather16pk(const unsigned* __restrict__ sw,
                                               int4 A, int4 B) {
    unsigned a = 0, w;
    w = (unsigned)A.x; a |= bitw(sw, w & 0xFFFFu) << 0;  a |= bitw(sw, w >> 16) << 1;
    w = (unsigned)A.y; a |= bitw(sw, w & 0xFFFFu) << 2;  a |= bitw(sw, w >> 16) << 3;
    w = (unsigned)A.z; a |= bitw(sw, w & 0xFFFFu) << 4;  a |= bitw(sw, w >> 16) << 5;
    w = (unsigned)A.w; a |= bitw(sw, w & 0xFFFFu) << 6;  a |= bitw(sw, w >> 16) << 7;
    w = (unsigned)B.x; a |= bitw(sw, w & 0xFFFFu) << 8;  a |= bitw(sw, w >> 16) << 9;
    w = (unsigned)B.y; a |= bitw(sw, w & 0xFFFFu) << 10; a |= bitw(sw, w >> 16) << 11;
    w = (unsigned)B.z; a |= bitw(sw, w & 0xFFFFu) << 12; a |= bitw(sw, w >> 16) << 13;
    w = (unsigned)B.w; a |= bitw(sw, w & 0xFFFFu) << 14; a |= bitw(sw, w >> 16) << 15;
    return a;
}

// Pack four i32 conn vectors (16 indices) into two int4s of u16 pairs.
__device__ __forceinline__ void pack8(int4 c0, int4 c1, int4 c2, int4 c3,
                                      int4& A, int4& B) {
    A.x = (int)(((unsigned)c0.x & 0xFFFFu) | ((unsigned)c0.y << 16));
    A.y = (int)(((unsigned)c0.z & 0xFFFFu) | ((unsigned)c0.w << 16));
    A.z = (int)(((unsigned)c1.x & 0xFFFFu) | ((unsigned)c1.y << 16));
    A.w = (int)(((unsigned)c1.z & 0xFFFFu) | ((unsigned)c1.w << 16));
    B.x = (int)(((unsigned)c2.x & 0xFFFFu) | ((unsigned)c2.y << 16));
    B.y = (int)(((unsigned)c2.z & 0xFFFFu) | ((unsigned)c2.w << 16));
    B.z = (int)(((unsigned)c3.x & 0xFFFFu) | ((unsigned)c3.y << 16));
    B.w = (int)(((unsigned)c3.z & 0xFFFFu) | ((unsigned)c3.w << 16));
}

__global__ __launch_bounds__(THREADS, 2)
void ram_multistep_kernel(
    const int* __restrict__ x,
    const int4* __restrict__ conn_in,
    const int4* __restrict__ conn_state,
    const int4* __restrict__ conn_out,
    const float* __restrict__ mem_in,
    const float* __restrict__ mem_state,
    const float* __restrict__ mem_out,
    float* __restrict__ out)
{
    __shared__ unsigned sx[32];       // 1024 input bits packed
    __shared__ unsigned sbufA[96];    // [0,64) in-bits, [64,96) state bits
    __shared__ unsigned sbufB[96];    // double buffer

    const int b = blockIdx.x;
    const int tid = threadIdx.x;
    const int lane = tid & 31;
    const int warp = tid >> 5;        // 0..7

    const unsigned long long pol_pin   = mk_policy_pin();
    const unsigned long long pol_state = mk_policy_state();

    // ---- Pack x bits (coalesced, ballot) ----
    #pragma unroll
    for (int r = 0; r < 4; r++) {
        int bit = __ldg(x + b * IN_BITS + r * 256 + tid);
        unsigned w = __ballot_sync(0xFFFFFFFFu, bit != 0);
        if (lane == 0) sx[r * 8 + warp] = w;
    }
    if (tid < 32) sbufA[64 + tid] = 0u;    // initial state = 0 (read by iter 0)
    __syncthreads();

    // ---- Hoist + register-pack state conn (overlaps in-phase; reused x4) ----
    int4 cs[8];                            // 4 neurons x 16 packed u16
    #pragma unroll
    for (int k = 0; k < 4; k++) {
        const int4* c = conn_state + (k * 256 + tid) * 4;
        int4 c0 = __ldg(c + 0), c1 = __ldg(c + 1), c2 = __ldg(c + 2), c3 = __ldg(c + 3);
        pack8(c0, c1, c2, c3, cs[2 * k], cs[2 * k + 1]);
    }

    // ---- Input layer: 2048 neurons, 8 per thread, i32 conn ----
    {
        unsigned addr[8];
        #pragma unroll
        for (int r = 0; r < 8; r++) {
            const int4* c = conn_in + (r * 256 + tid) * 4;
            int4 c0 = __ldg(c + 0), c1 = __ldg(c + 1), c2 = __ldg(c + 2), c3 = __ldg(c + 3);
            addr[r] = gather16i(sx, c0, c1, c2, c3);
        }
        float v[8];
        #pragma unroll
        for (int r = 0; r < 8; r++) {
            int n = r * 256 + tid;
            v[r] = ld_tbl64(mem_in + (size_t)n * TBL + addr[r], pol_pin);
        }
        #pragma unroll
        for (int r = 0; r < 8; r++) {
            unsigned w = __ballot_sync(0xFFFFFFFFu, v[r] > 0.5f);
            if (lane == 0) { sbufA[r * 8 + warp] = w; sbufB[r * 8 + warp] = w; }
        }
    }

    // ---- Hoist + register-pack out conn before the state loop ----
    int4 co[4];                            // 2 neurons x 16 packed u16
    #pragma unroll
    for (int r = 0; r < 2; r++) {
        const int4* c = conn_out + (r * 256 + tid) * 4;
        int4 c0 = __ldg(c + 0), c1 = __ldg(c + 1), c2 = __ldg(c + 2), c3 = __ldg(c + 3);
        pack8(c0, c1, c2, c3, co[2 * r], co[2 * r + 1]);
    }
    __syncthreads();

    // ---- Recurrent state iterations: 4 per thread, 1 barrier/iter ----
    unsigned* cur = sbufA;
    unsigned* nxt = sbufB;
    for (int it = 0; it < MAX_ITERS; it++) {
        unsigned addr[4];
        #pragma unroll
        for (int k = 0; k < 4; k++)
            addr[k] = gather16pk(cur, cs[2 * k], cs[2 * k + 1]);
        float v[4];
        #pragma unroll
        for (int k = 0; k < 4; k++) {
            int n = k * 256 + tid;
            v[k] = ld_tbl64(mem_state + (size_t)n * TBL + addr[k], pol_state);
        }
        #pragma unroll
        for (int k = 0; k < 4; k++) {
            unsigned w = __ballot_sync(0xFFFFFFFFu, v[k] > 0.5f);
            if (lane == 0) nxt[64 + k * 8 + warp] = w;   // disjoint from cur
        }
        __syncthreads();                 // nxt complete & visible
        unsigned* t = cur; cur = nxt; nxt = t;
    }

    // ---- Output layer: 512 neurons, 2 per thread (final state only) ----
    {
        unsigned addr[2];
        #pragma unroll
        for (int r = 0; r < 2; r++)
            addr[r] = gather16pk(cur, co[2 * r], co[2 * r + 1]);
        #pragma unroll
        for (int r = 0; r < 2; r++) {
            int n = r * 256 + tid;
            out[b * N_OUT + n] = ld_tbl64(mem_out + (size_t)n * TBL + addr[r], pol_pin);
        }
    }
}

extern "C" void kernel_launch(void* const* d_in, const int* in_sizes, int n_in,
                              void* d_out, int out_size) {
    const int* x            = (const int*)d_in[0];
    const int4* conn_in     = (const int4*)d_in[1];
    const int4* conn_state  = (const int4*)d_in[2];
    const int4* conn_out    = (const int4*)d_in[3];
    const float* mem_in     = (const float*)d_in[4];
    const float* mem_state  = (const float*)d_in[5];
    const float* mem_out    = (const float*)d_in[6];
    float* out = (float*)d_out;

    ram_multistep_kernel<<<BATCH, THREADS>>>(x, conn_in, conn_state, conn_out,
                                             mem_in, mem_state, mem_out, out);
}